// round 1
// baseline (speedup 1.0000x reference)
#include <cuda_runtime.h>

// Problem shape (fixed by the dataset)
#define W_  1920
#define H_  1080
#define B_  4
#define C_  3
constexpr int HW = H_ * W_;     // 2,073,600
constexpr int N  = B_ * HW;     // 8,294,400

// Scratch (cudaMalloc is forbidden -> static device globals)
__device__ int   g_dbuf[N];          // quantized motion-magnitude depth buffer
__device__ float g_wght[N];          // splat weight accumulator
__device__ float g_accum[3 * N];     // per-channel value accumulator [C][N]

// ---------------------------------------------------------------------------
// Pass 0: zero all scratch (vectorized 16B stores)
// ---------------------------------------------------------------------------
__global__ void k_init()
{
    int i = blockIdx.x * blockDim.x + threadIdx.x;
    const int4 z = make_int4(0, 0, 0, 0);
    if (i < N / 4) {
        reinterpret_cast<int4*>(g_dbuf)[i] = z;
        reinterpret_cast<int4*>(g_wght)[i] = z;
    }
    if (i < 3 * N / 4) {
        reinterpret_cast<int4*>(g_accum)[i] = z;
    }
}

// ---------------------------------------------------------------------------
// Pass 1: scatter-max depth buffer.
// NOTE: all 4 in-bounds corners participate regardless of bilinear weight --
// a zero-weight corner can still suppress other pixels' contributions.
// ---------------------------------------------------------------------------
__global__ void __launch_bounds__(256) k_depth(const float2* __restrict__ flow)
{
    int i = blockIdx.x * blockDim.x + threadIdx.x;
    if (i >= N) return;

    int b = i / HW;
    int p = i - b * HW;
    int h = p / W_;
    int w = p - h * W_;

    float2 f = flow[i];
    float x = (float)w + f.x;
    float y = (float)h + f.y;
    int x0 = (int)floorf(x);
    int y0 = (int)floorf(y);

    // depth key: round-half-even (matches jnp.round), IEEE sqrt regardless of fast-math
    int d = __float2int_rn(__fsqrt_rn(f.x * f.x + f.y * f.y) * 1000.0f);

    int base = b * HW;
#pragma unroll
    for (int dy = 0; dy < 2; dy++) {
#pragma unroll
        for (int dx = 0; dx < 2; dx++) {
            int tx = x0 + dx;
            int ty = y0 + dy;
            if (tx >= 0 && tx < W_ && ty >= 0 && ty < H_) {
                atomicMax(&g_dbuf[base + ty * W_ + tx], d);
            }
        }
    }
}

// ---------------------------------------------------------------------------
// Pass 2: accumulate contributions that win the depth test.
// ---------------------------------------------------------------------------
__global__ void __launch_bounds__(256) k_accum(const float* __restrict__ im0,
                                               const float2* __restrict__ flow)
{
    int i = blockIdx.x * blockDim.x + threadIdx.x;
    if (i >= N) return;

    int b = i / HW;
    int p = i - b * HW;
    int h = p / W_;
    int w = p - h * W_;

    float2 f = flow[i];
    float x = (float)w + f.x;
    float y = (float)h + f.y;
    float x0f = floorf(x);
    float y0f = floorf(y);
    float ax = x - x0f;
    float ay = y - y0f;
    int x0 = (int)x0f;
    int y0 = (int)y0f;

    int d = __float2int_rn(__fsqrt_rn(f.x * f.x + f.y * f.y) * 1000.0f);

    // source pixel values (3 channels)
    const float* src = im0 + (size_t)b * 3 * HW + p;
    float v0 = src[0];
    float v1 = src[HW];
    float v2 = src[2 * HW];

    float wx1 = ax, wx0 = 1.0f - ax;
    float wy1 = ay, wy0 = 1.0f - ay;
    float wts[4] = { wx0 * wy0, wx1 * wy0, wx0 * wy1, wx1 * wy1 };
    int   txs[4] = { x0, x0 + 1, x0,     x0 + 1 };
    int   tys[4] = { y0, y0,     y0 + 1, y0 + 1 };

    int base = b * HW;
#pragma unroll
    for (int k = 0; k < 4; k++) {
        int tx = txs[k];
        int ty = tys[k];
        if (tx < 0 || tx >= W_ || ty < 0 || ty >= H_) continue;
        int idx = base + ty * W_ + tx;
        if (g_dbuf[idx] != d) continue;      // depth test (d >= 0 always)
        float wv = wts[k];
        if (wv == 0.0f) continue;            // adding exact 0.0 is an identity
        atomicAdd(&g_wght[idx], wv);
        atomicAdd(&g_accum[idx],         wv * v0);
        atomicAdd(&g_accum[N + idx],     wv * v1);
        atomicAdd(&g_accum[2 * N + idx], wv * v2);
    }
}

// ---------------------------------------------------------------------------
// Pass 3: normalize -> out[b][c][h][w] = accum[c][b*HW+p] / max(wght, eps)
// ---------------------------------------------------------------------------
__global__ void __launch_bounds__(256) k_norm(float* __restrict__ out)
{
    int i = blockIdx.x * blockDim.x + threadIdx.x;
    if (i >= N) return;

    int b = i / HW;
    int p = i - b * HW;

    float wv  = g_wght[i];
    float inv = 1.0f / fmaxf(wv, 1e-5f);

    float* dst = out + (size_t)b * 3 * HW + p;
    dst[0]      = g_accum[i]         * inv;
    dst[HW]     = g_accum[N + i]     * inv;
    dst[2 * HW] = g_accum[2 * N + i] * inv;
}

// ---------------------------------------------------------------------------
extern "C" void kernel_launch(void* const* d_in, const int* in_sizes, int n_in,
                              void* d_out, int out_size)
{
    const float*  im0  = (const float*)d_in[0];   // [B,C,H,W] float32
    const float2* flow = (const float2*)d_in[1];  // [B,H,W,2] float32
    float*        out  = (float*)d_out;           // [B,C,H,W] float32

    const int T = 256;
    int init_threads = (3 * N) / 4;               // covers all three zero loops
    k_init <<<(init_threads + T - 1) / T, T>>>();
    k_depth<<<(N + T - 1) / T, T>>>(flow);
    k_accum<<<(N + T - 1) / T, T>>>(im0, flow);
    k_norm <<<(N + T - 1) / T, T>>>(out);

    (void)in_sizes; (void)n_in; (void)out_size;
}

// round 2
// speedup vs baseline: 1.3262x; 1.3262x over previous
#include <cuda_runtime.h>

// Problem shape (fixed by the dataset)
#define W_  1920
#define H_  1080
#define B_  4
#define C_  3
constexpr int HW = H_ * W_;     // 2,073,600
constexpr int N  = B_ * HW;     // 8,294,400

// Scratch (cudaMalloc is forbidden -> static device globals)
__device__ int                  g_dbuf[N];   // quantized motion-magnitude depth buffer
__device__ __align__(16) float4 g_acc[N];    // AoS: {weight, c0, c1, c2} per pixel

// One 16-byte vector reduction instead of 4 scalar float atomics.
__device__ __forceinline__ void red_add_v4(float4* p, float a, float b, float c, float d)
{
    asm volatile("red.global.add.v4.f32 [%0], {%1, %2, %3, %4};"
                 :: "l"(p), "f"(a), "f"(b), "f"(c), "f"(d) : "memory");
}

// ---------------------------------------------------------------------------
// Pass 0: zero the depth buffer only (accumulator zeroing is fused into k_depth)
// ---------------------------------------------------------------------------
__global__ void k_init_dbuf()
{
    int i = blockIdx.x * blockDim.x + threadIdx.x;
    if (i < N / 4)
        reinterpret_cast<int4*>(g_dbuf)[i] = make_int4(0, 0, 0, 0);
}

// ---------------------------------------------------------------------------
// Pass 1: scatter-max depth buffer + stream-zero the accumulator.
// All 4 in-bounds corners participate regardless of bilinear weight --
// a zero-weight corner can still suppress other pixels' contributions.
// ---------------------------------------------------------------------------
__global__ void __launch_bounds__(256) k_depth(const float2* __restrict__ flow)
{
    int i = blockIdx.x * blockDim.x + threadIdx.x;
    if (i >= N) return;

    // fused accumulator zeroing (STG.128, rides the store path)
    g_acc[i] = make_float4(0.f, 0.f, 0.f, 0.f);

    int b = i / HW;
    int p = i - b * HW;
    int h = p / W_;
    int w = p - h * W_;

    float2 f = flow[i];
    float x = (float)w + f.x;
    float y = (float)h + f.y;
    int x0 = (int)floorf(x);
    int y0 = (int)floorf(y);

    // depth key: round-half-even (matches jnp.round), IEEE sqrt regardless of fast-math
    int d = __float2int_rn(__fsqrt_rn(f.x * f.x + f.y * f.y) * 1000.0f);

    int base = b * HW;
#pragma unroll
    for (int dy = 0; dy < 2; dy++) {
#pragma unroll
        for (int dx = 0; dx < 2; dx++) {
            int tx = x0 + dx;
            int ty = y0 + dy;
            if (tx >= 0 && tx < W_ && ty >= 0 && ty < H_)
                atomicMax(&g_dbuf[base + ty * W_ + tx], d);
        }
    }
}

// ---------------------------------------------------------------------------
// Pass 2: accumulate depth-test winners with ONE vec4 reduction per corner.
// ---------------------------------------------------------------------------
__global__ void __launch_bounds__(256) k_accum(const float* __restrict__ im0,
                                               const float2* __restrict__ flow)
{
    int i = blockIdx.x * blockDim.x + threadIdx.x;
    if (i >= N) return;

    int b = i / HW;
    int p = i - b * HW;
    int h = p / W_;
    int w = p - h * W_;

    float2 f = flow[i];
    float x = (float)w + f.x;
    float y = (float)h + f.y;
    float x0f = floorf(x);
    float y0f = floorf(y);
    float ax = x - x0f;
    float ay = y - y0f;
    int x0 = (int)x0f;
    int y0 = (int)y0f;

    int d = __float2int_rn(__fsqrt_rn(f.x * f.x + f.y * f.y) * 1000.0f);

    // source pixel values (3 channels, planar)
    const float* src = im0 + (size_t)b * 3 * HW + p;
    float v0 = __ldg(src);
    float v1 = __ldg(src + HW);
    float v2 = __ldg(src + 2 * HW);

    float wx1 = ax, wx0 = 1.0f - ax;
    float wy1 = ay, wy0 = 1.0f - ay;
    float wts[4] = { wx0 * wy0, wx1 * wy0, wx0 * wy1, wx1 * wy1 };
    int   txs[4] = { x0, x0 + 1, x0,     x0 + 1 };
    int   tys[4] = { y0, y0,     y0 + 1, y0 + 1 };

    int base = b * HW;
#pragma unroll
    for (int k = 0; k < 4; k++) {
        int tx = txs[k];
        int ty = tys[k];
        if (tx < 0 || tx >= W_ || ty < 0 || ty >= H_) continue;
        int idx = base + ty * W_ + tx;
        if (__ldg(&g_dbuf[idx]) != d) continue;   // depth test (d >= 0 always)
        float wv = wts[k];
        if (wv == 0.0f) continue;                 // adding exact 0.0 is an identity
        red_add_v4(&g_acc[idx], wv, wv * v0, wv * v1, wv * v2);
    }
}

// ---------------------------------------------------------------------------
// Pass 3: normalize. 4 pixels per thread: 4x LDG.128 in, 3x STG.128 out.
// out[b][c][h][w] = acc.c / max(acc.w, eps)
// ---------------------------------------------------------------------------
__global__ void __launch_bounds__(256) k_norm(float* __restrict__ out)
{
    int t = blockIdx.x * blockDim.x + threadIdx.x;
    if (t >= N / 4) return;

    int i  = t * 4;           // first pixel of this group (HW % 4 == 0 -> never crosses b)
    int b  = i / HW;
    int p  = i - b * HW;

    float4 a0 = g_acc[i];
    float4 a1 = g_acc[i + 1];
    float4 a2 = g_acc[i + 2];
    float4 a3 = g_acc[i + 3];

    float r0 = 1.0f / fmaxf(a0.x, 1e-5f);
    float r1 = 1.0f / fmaxf(a1.x, 1e-5f);
    float r2 = 1.0f / fmaxf(a2.x, 1e-5f);
    float r3 = 1.0f / fmaxf(a3.x, 1e-5f);

    float* dst = out + (size_t)b * 3 * HW + p;    // p % 4 == 0 -> 16B aligned
    reinterpret_cast<float4*>(dst)[0]              = make_float4(a0.y * r0, a1.y * r1, a2.y * r2, a3.y * r3);
    reinterpret_cast<float4*>(dst + HW)[0]         = make_float4(a0.z * r0, a1.z * r1, a2.z * r2, a3.z * r3);
    reinterpret_cast<float4*>(dst + 2 * HW)[0]     = make_float4(a0.w * r0, a1.w * r1, a2.w * r2, a3.w * r3);
}

// ---------------------------------------------------------------------------
extern "C" void kernel_launch(void* const* d_in, const int* in_sizes, int n_in,
                              void* d_out, int out_size)
{
    const float*  im0  = (const float*)d_in[0];   // [B,C,H,W] float32
    const float2* flow = (const float2*)d_in[1];  // [B,H,W,2] float32
    float*        out  = (float*)d_out;           // [B,C,H,W] float32

    const int T = 256;
    k_init_dbuf<<<(N / 4 + T - 1) / T, T>>>();
    k_depth    <<<(N + T - 1) / T, T>>>(flow);
    k_accum    <<<(N + T - 1) / T, T>>>(im0, flow);
    k_norm     <<<(N / 4 + T - 1) / T, T>>>(out);

    (void)in_sizes; (void)n_in; (void)out_size;
}